// round 16
// baseline (speedup 1.0000x reference)
#include <cuda_runtime.h>
#include <cstdint>

// Problem constants
#define BATCH 2
#define QLEN  4096
#define FDIM  512
#define HEADS 8
#define DDIM  64
#define MROWS (BATCH * QLEN)          // 8192
#define BHROWS (BATCH * HEADS * QLEN) // 65536

// GEMM activation/weight planes: k-block layout [kb][row][16], seg-swizzled
__device__ uint32_t g_xq_h[(size_t)MROWS * 256],  g_xq_l[(size_t)MROWS * 256];
__device__ uint32_t g_xkv_h[(size_t)MROWS * 256], g_xkv_l[(size_t)MROWS * 256];
__device__ uint32_t g_wq_h[512 * 256], g_wq_l[512 * 256];
__device__ uint32_t g_wk_h[512 * 256], g_wk_l[512 * 256];
__device__ uint32_t g_wv_h[512 * 256], g_wv_l[512 * 256];
__device__ uint32_t g_wo_h[512 * 256], g_wo_l[512 * 256];
// Q/K/V planes: flash layout [row][32], 16B-seg XOR (row&7)
__device__ uint32_t g_qh[(size_t)BHROWS * 32], g_ql[(size_t)BHROWS * 32];
__device__ uint32_t g_kh[(size_t)BHROWS * 32], g_kl[(size_t)BHROWS * 32];
__device__ uint32_t g_vh[(size_t)BHROWS * 32], g_vl[(size_t)BHROWS * 32];
// O planes: k-block layout (input to gemm_out)
__device__ uint32_t g_oh[(size_t)MROWS * 256],  g_ol[(size_t)MROWS * 256];
__device__ int g_ctr;   // flash work-stealing counter

// ===========================================================================
// Helpers
// ===========================================================================
__device__ __forceinline__ uint32_t smem_u32(const void* p) {
    uint32_t a;
    asm("{ .reg .u64 t; cvta.to.shared.u64 t, %1; cvt.u32.u64 %0, t; }"
        : "=r"(a) : "l"(p));
    return a;
}
__device__ __forceinline__ uint32_t packbf(float a, float b) {  // low = a
    uint32_t r;
    asm("cvt.rn.bf16x2.f32 %0, %1, %2;" : "=r"(r) : "f"(b), "f"(a));
    return r;
}
__device__ __forceinline__ float lof(uint32_t h) { return __uint_as_float(h << 16); }
__device__ __forceinline__ float hif(uint32_t h) { return __uint_as_float(h & 0xffff0000u); }

__device__ __forceinline__ void ldsm4(uint32_t (&r)[4], uint32_t addr) {
    asm volatile("ldmatrix.sync.aligned.m8n8.x4.shared.b16 {%0,%1,%2,%3}, [%4];"
                 : "=r"(r[0]), "=r"(r[1]), "=r"(r[2]), "=r"(r[3]) : "r"(addr));
}
__device__ __forceinline__ void ldsm4t(uint32_t (&r)[4], uint32_t addr) {
    asm volatile("ldmatrix.sync.aligned.m8n8.x4.trans.shared.b16 {%0,%1,%2,%3}, [%4];"
                 : "=r"(r[0]), "=r"(r[1]), "=r"(r[2]), "=r"(r[3]) : "r"(addr));
}
__device__ __forceinline__ void mma16816(float (&d)[4], const uint32_t (&a)[4],
                                         uint32_t b0, uint32_t b1) {
    asm volatile(
        "mma.sync.aligned.m16n8k16.row.col.f32.bf16.bf16.f32 "
        "{%0,%1,%2,%3}, {%4,%5,%6,%7}, {%8,%9}, {%0,%1,%2,%3};"
        : "+f"(d[0]), "+f"(d[1]), "+f"(d[2]), "+f"(d[3])
        : "r"(a[0]), "r"(a[1]), "r"(a[2]), "r"(a[3]), "r"(b0), "r"(b1));
}
// mbarrier + bulk copy (sm_90 base)
__device__ __forceinline__ void mbar_init(uint32_t a, uint32_t n) {
    asm volatile("mbarrier.init.shared.b64 [%0], %1;" :: "r"(a), "r"(n) : "memory");
}
__device__ __forceinline__ void mbar_expect(uint32_t a, uint32_t bytes) {
    asm volatile("mbarrier.arrive.expect_tx.shared.b64 _, [%0], %1;"
                 :: "r"(a), "r"(bytes) : "memory");
}
__device__ __forceinline__ void mbar_wait(uint32_t a, uint32_t parity) {
    asm volatile(
        "{\n\t.reg .pred P;\n\t"
        "WL%=:\n\t"
        "mbarrier.try_wait.parity.acquire.cta.shared::cta.b64 P, [%0], %1, 0x989680;\n\t"
        "@P bra.uni WD%=;\n\t"
        "bra.uni WL%=;\n\t"
        "WD%=:\n\t}"
        :: "r"(a), "r"(parity) : "memory");
}
__device__ __forceinline__ void bulk_g2s(uint32_t dst, const void* src,
                                         uint32_t bytes, uint32_t mbar) {
    asm volatile(
        "cp.async.bulk.shared::cta.global.mbarrier::complete_tx::bytes "
        "[%0], [%1], %2, [%3];"
        :: "r"(dst), "l"(src), "r"(bytes), "r"(mbar) : "memory");
}

// ===========================================================================
// Prep: fp32 -> bf16 hi/lo planes in k-block layout [kb][row][16], swizzled
// ===========================================================================
__global__ void reset_ctr() { g_ctr = 0; }

__global__ void prep_act2(const float* __restrict__ s0, const float* __restrict__ s1,
                          uint32_t* __restrict__ h0, uint32_t* __restrict__ l0p,
                          uint32_t* __restrict__ h1, uint32_t* __restrict__ l1p) {
    int blk = blockIdx.x;
    int row = blk & (MROWS - 1);
    const float* src = (blk < MROWS) ? s0 : s1;
    uint32_t* dh = (blk < MROWS) ? h0 : h1;
    uint32_t* dl = (blk < MROWS) ? l0p : l1p;
    int kp = threadIdx.x;                 // 0..255
    float2 v = ((const float2*)src)[(size_t)row * 256 + kp];
    uint32_t h = packbf(v.x, v.y);
    uint32_t l = packbf(v.x - lof(h), v.y - hif(h));
    int kb = kp >> 4, kpi = kp & 15;
    int seg = (kpi >> 2) ^ ((row >> 1) & 3);
    size_t dst = ((size_t)kb * MROWS + row) * 16 + seg * 4 + (kpi & 3);
    dh[dst] = h;
    dl[dst] = l;
}
__global__ void prep_w4(const float* __restrict__ W0, const float* __restrict__ W1,
                        const float* __restrict__ W2, const float* __restrict__ W3,
                        uint32_t* __restrict__ H0, uint32_t* __restrict__ L0,
                        uint32_t* __restrict__ H1, uint32_t* __restrict__ L1,
                        uint32_t* __restrict__ H2, uint32_t* __restrict__ L2,
                        uint32_t* __restrict__ H3, uint32_t* __restrict__ L3) {
    int blk = blockIdx.x;
    int sel = blk >> 9;
    const float* W = sel == 0 ? W0 : sel == 1 ? W1 : sel == 2 ? W2 : W3;
    uint32_t* dh   = sel == 0 ? H0 : sel == 1 ? H1 : sel == 2 ? H2 : H3;
    uint32_t* dl   = sel == 0 ? L0 : sel == 1 ? L1 : sel == 2 ? L2 : L3;
    int t = (blk & 511) * 256 + threadIdx.x;
    int n = t & 511, kp = t >> 9;
    float a = W[(size_t)(2 * kp) * 512 + n];
    float b = W[(size_t)(2 * kp + 1) * 512 + n];
    uint32_t h = packbf(a, b);
    uint32_t l = packbf(a - lof(h), b - hif(h));
    int kb = kp >> 4, kpi = kp & 15;
    int seg = (kpi >> 2) ^ ((n >> 1) & 3);
    size_t dst = ((size_t)kb * 512 + n) * 16 + seg * 4 + (kpi & 3);
    dh[dst] = h;
    dl[dst] = l;
}

// ===========================================================================
// GEMM core: BM=128 BN=128 BK=32, bulk-copy 2-deep pipeline.
// Stage (32768B): AH 0 | AL 8192 | WH 16384 | WL 24576 ; packed 64B rows.
// Warp tile 32x64 (4m x 2n warps).
// ===========================================================================
#define GSTG 32768
#define GEMM_SMEM (2 * GSTG)

__device__ __forceinline__ void gemm_bulk(
    uint32_t buf, int kb,
    const uint32_t* __restrict__ Ah, const uint32_t* __restrict__ Al,
    const uint32_t* __restrict__ Wh, const uint32_t* __restrict__ Wl,
    int rowBase, int colBase, uint32_t mb)
{
    mbar_expect(mb, 32768u);
    bulk_g2s(buf,          Ah + ((size_t)kb * MROWS + rowBase) * 16, 8192u, mb);
    bulk_g2s(buf + 8192u,  Al + ((size_t)kb * MROWS + rowBase) * 16, 8192u, mb);
    bulk_g2s(buf + 16384u, Wh + ((size_t)kb * 512 + colBase) * 16,   8192u, mb);
    bulk_g2s(buf + 24576u, Wl + ((size_t)kb * 512 + colBase) * 16,   8192u, mb);
}

__device__ __forceinline__ void gemm_main(
    float (&o)[16][4], uint32_t smb, uint32_t mb0, uint32_t mb1,
    const uint32_t* __restrict__ Ah, const uint32_t* __restrict__ Al,
    const uint32_t* __restrict__ Wh, const uint32_t* __restrict__ Wl,
    int rowBase, int colBase, int tid, int wm, int wn,
    int r8, int s01, int s23)
{
    if (tid == 0) {
        gemm_bulk(smb,        0, Ah, Al, Wh, Wl, rowBase, colBase, mb0);
        gemm_bulk(smb + GSTG, 1, Ah, Al, Wh, Wl, rowBase, colBase, mb1);
    }
    int ph0 = 0, ph1 = 0;

    // per-lane row indices and swizzle factors (A: 2 m-tiles; W: 4 n-tiles)
    int arow0 = wm * 32 + s01 * 8 + r8;
    int arow1 = arow0 + 16;
    const uint32_t asw0 = (uint32_t)((arow0 >> 1) & 3);
    const uint32_t asw1 = (uint32_t)((arow1 >> 1) & 3);

    for (int it = 0; it < 16; ++it) {
        const uint32_t mb = (it & 1) ? mb1 : mb0;
        if (it & 1) { mbar_wait(mb, ph1); ph1 ^= 1; }
        else        { mbar_wait(mb, ph0); ph0 ^= 1; }
        const uint32_t bb = smb + (uint32_t)(it & 1) * GSTG;

#pragma unroll
        for (int kc = 0; kc < 2; ++kc) {
            uint32_t ah4[2][4], al4[2][4];
            {
                uint32_t a0 = bb + (uint32_t)(arow0 * 64) +
                              ((((uint32_t)(kc * 2) | (uint32_t)s23) ^ asw0) << 4);
                uint32_t a1 = bb + (uint32_t)(arow1 * 64) +
                              ((((uint32_t)(kc * 2) | (uint32_t)s23) ^ asw1) << 4);
                ldsm4(ah4[0], a0);
                ldsm4(al4[0], a0 + 8192u);
                ldsm4(ah4[1], a1);
                ldsm4(al4[1], a1 + 8192u);
            }
#pragma unroll
            for (int ng = 0; ng < 4; ++ng) {
                const int wrow = wn * 64 + ng * 16 + s23 * 8 + r8;
                const uint32_t wsw = (uint32_t)((wrow >> 1) & 3);
                const uint32_t wa = bb + 16384u + (uint32_t)(wrow * 64) +
                    ((((uint32_t)(kc * 2) | (uint32_t)s01) ^ wsw) << 4);
                uint32_t wh[4], wl[4];
                ldsm4(wh, wa);
                ldsm4(wl, wa + 8192u);
                mma16816(o[0 * 8 + ng * 2 + 0], ah4[0], wh[0], wh[1]);
                mma16816(o[0 * 8 + ng * 2 + 1], ah4[0], wh[2], wh[3]);
                mma16816(o[1 * 8 + ng * 2 + 0], ah4[1], wh[0], wh[1]);
                mma16816(o[1 * 8 + ng * 2 + 1], ah4[1], wh[2], wh[3]);
                mma16816(o[0 * 8 + ng * 2 + 0], al4[0], wh[0], wh[1]);
                mma16816(o[0 * 8 + ng * 2 + 1], al4[0], wh[2], wh[3]);
                mma16816(o[1 * 8 + ng * 2 + 0], al4[1], wh[0], wh[1]);
                mma16816(o[1 * 8 + ng * 2 + 1], al4[1], wh[2], wh[3]);
                mma16816(o[0 * 8 + ng * 2 + 0], ah4[0], wl[0], wl[1]);
                mma16816(o[0 * 8 + ng * 2 + 1], ah4[0], wl[2], wl[3]);
                mma16816(o[1 * 8 + ng * 2 + 0], ah4[1], wl[0], wl[1]);
                mma16816(o[1 * 8 + ng * 2 + 1], ah4[1], wl[2], wl[3]);
            }
        }
        __syncthreads();        // all reads of buf(it) done
        if (it + 2 < 16 && tid == 0)
            gemm_bulk(bb, it + 2, Ah, Al, Wh, Wl, rowBase, colBase, mb);
    }
}

// Fused QKV projection; epilogue writes flash-swizzled q/k/v planes.
__global__ __launch_bounds__(256, 2) void gemm_qkv(
    const uint32_t* __restrict__ xqh, const uint32_t* __restrict__ xql,
    const uint32_t* __restrict__ xkvh, const uint32_t* __restrict__ xkvl,
    const uint32_t* __restrict__ wqh, const uint32_t* __restrict__ wql,
    const uint32_t* __restrict__ wkh, const uint32_t* __restrict__ wkl,
    const uint32_t* __restrict__ wvh, const uint32_t* __restrict__ wvl,
    uint32_t* __restrict__ qh, uint32_t* __restrict__ ql,
    uint32_t* __restrict__ kh, uint32_t* __restrict__ kl,
    uint32_t* __restrict__ vh, uint32_t* __restrict__ vl)
{
    extern __shared__ char sm[];
    __shared__ __align__(8) unsigned long long gbar[2];
    const int tid = threadIdx.x;
    const int w = tid >> 5, lane = tid & 31;
    const int g = lane >> 2, tig = lane & 3;
    const int r8 = lane & 7;
    const int s01 = (lane >> 3) & 1;
    const int s23 = lane >> 4;
    const int rowBase = blockIdx.y * 128;
    const int colBase = blockIdx.x * 128;
    const int z = blockIdx.z;
    const int wm = w >> 1, wn = w & 1;

    const uint32_t smb = smem_u32(sm);
    const uint32_t mb0 = smem_u32(&gbar[0]);
    const uint32_t mb1 = smem_u32(&gbar[1]);
    if (tid == 0) { mbar_init(mb0, 1); mbar_init(mb1, 1); }
    __syncthreads();

    const uint32_t* Ah = (z == 0) ? xqh : xkvh;
    const uint32_t* Al = (z == 0) ? xql : xkvl;
    const uint32_t* Wh = (z == 0) ? wqh : (z == 1) ? wkh : wvh;
    const uint32_t* Wl = (z == 0) ? wql : (z == 1) ? wkl : wvl;
    uint32_t* Ch = (z == 0) ? qh : (z == 1) ? kh : vh;
    uint32_t* Cl = (z == 0) ? ql : (z == 1) ? kl : vl;

    float o[16][4];
#pragma unroll
    for (int i = 0; i < 16; ++i)
#pragma unroll
        for (int j = 0; j < 4; ++j) o[i][j] = 0.f;

    gemm_main(o, smb, mb0, mb1, Ah, Al, Wh, Wl, rowBase, colBase,
              tid, wm, wn, r8, s01, s23);

#pragma unroll
    for (int dt = 0; dt < 16; ++dt) {
        const int mt = dt >> 3, ng = (dt >> 1) & 3, s = dt & 1;
        const int qr = rowBase + wm * 32 + mt * 16 + g;
        const int ncol = colBase + wn * 64 + ng * 16 + s * 8 + tig * 2;
        const int bb_ = qr >> 12;
        const int l = qr & 4095;
        const int hh = ncol >> 6;
        const int dpair = (ncol & 63) >> 1;
        // flash swizzle: 16B seg XOR (row & 7)
        const int dsw = ((((dpair >> 2) ^ (l & 7)) << 2) | (dpair & 3));
        const size_t prow0 = ((size_t)bb_ * HEADS + hh) * 4096 + l;
        const size_t prow1 = prow0 + 8;
        uint32_t h0 = packbf(o[dt][0], o[dt][1]);
        uint32_t l0_ = packbf(o[dt][0] - lof(h0), o[dt][1] - hif(h0));
        uint32_t h1 = packbf(o[dt][2], o[dt][3]);
        uint32_t l1_ = packbf(o[dt][2] - lof(h1), o[dt][3] - hif(h1));
        Ch[prow0 * 32 + dsw] = h0; Cl[prow0 * 32 + dsw] = l0_;
        Ch[prow1 * 32 + dsw] = h1; Cl[prow1 * 32 + dsw] = l1_;
    }
}

// Output projection: fp32 row-major store
__global__ __launch_bounds__(256, 2) void gemm_out(
    const uint32_t* __restrict__ Ah, const uint32_t* __restrict__ Al,
    const uint32_t* __restrict__ Wh, const uint32_t* __restrict__ Wl,
    float* __restrict__ Cf)
{
    extern __shared__ char sm[];
    __shared__ __align__(8) unsigned long long gbar[2];
    const int tid = threadIdx.x;
    const int w = tid >> 5, lane = tid & 31;
    const int g = lane >> 2, tig = lane & 3;
    const int r8 = lane & 7;
    const int s01 = (lane >> 3) & 1;
    const int s23 = lane >> 4;
    const int rowBase = blockIdx.y * 128;
    const int colBase = blockIdx.x * 128;
    const int wm = w >> 1, wn = w & 1;

    const uint32_t smb = smem_u32(sm);
    const uint32_t mb0 = smem_u32(&gbar[0]);
    const uint32_t mb1 = smem_u32(&gbar[1]);
    if (tid == 0) { mbar_init(mb0, 1); mbar_init(mb1, 1); }
    __syncthreads();

    float o[16][4];
#pragma unroll
    for (int i = 0; i < 16; ++i)
#pragma unroll
        for (int j = 0; j < 4; ++j) o[i][j] = 0.f;

    gemm_main(o, smb, mb0, mb1, Ah, Al, Wh, Wl, rowBase, colBase,
              tid, wm, wn, r8, s01, s23);

#pragma unroll
    for (int dt = 0; dt < 16; ++dt) {
        const int mt = dt >> 3, ng = (dt >> 1) & 3, s = dt & 1;
        const int qr = rowBase + wm * 32 + mt * 16 + g;
        const int n = colBase + wn * 64 + ng * 16 + s * 8 + tig * 2;
        float2 v0; v0.x = o[dt][0]; v0.y = o[dt][1];
        float2 v1; v1.x = o[dt][2]; v1.y = o[dt][3];
        *(float2*)(Cf + (size_t)qr * FDIM + n) = v0;
        *(float2*)(Cf + (size_t)(qr + 8) * FDIM + n) = v1;
    }
}

// ===========================================================================
// Flash attention: persistent work-stealing, bulk copies (unchanged from R15
// except O epilogue writes k-block layout planes for gemm_out).
// SMEM: K hi @0, K lo @16384, V hi @32768, V lo @49152
// ===========================================================================
#define EXP_SHIFT 30.0f
#define SKH 0u
#define SKL 16384u
#define SVH 32768u
#define SVL 49152u
#define FLASH_SMEM 65536
#define FLASH_ITEMS 512
#define FLASH_GRID 296

__global__ __launch_bounds__(256, 2) void flash_mma(
    const uint32_t* __restrict__ qh, const uint32_t* __restrict__ ql,
    const uint32_t* __restrict__ kh, const uint32_t* __restrict__ kl,
    const uint32_t* __restrict__ vh, const uint32_t* __restrict__ vl,
    uint32_t* __restrict__ oh, uint32_t* __restrict__ ol)
{
    extern __shared__ char sm[];
    __shared__ __align__(8) unsigned long long smbar[3];  // q, k, v
    __shared__ int s_item;
    const int tid = threadIdx.x;
    const int w = tid >> 5, lane = tid & 31;
    const int g = lane >> 2, tig = lane & 3;
    const int r8 = lane & 7;
    const int s01 = (lane >> 3) & 1;
    const int s23 = lane >> 4;

    const uint32_t smb = smem_u32(sm);
    const uint32_t qb = smem_u32(&smbar[0]);
    const uint32_t kb = smem_u32(&smbar[1]);
    const uint32_t vb = smem_u32(&smbar[2]);
    if (tid == 0) { mbar_init(qb, 1); mbar_init(kb, 1); mbar_init(vb, 1); }
    __syncthreads();
    int qpar = 0, kpar = 0, vpar = 0;

    const uint32_t qrow = (uint32_t)((w * 16 + s01 * 8 + r8) * 128);
    const uint32_t krow = (uint32_t)((s23 * 8 + r8) * 128);
    const uint32_t vrow = (uint32_t)((s01 * 8 + r8) * 128);

    while (true) {
        if (tid == 0) s_item = atomicAdd(&g_ctr, 1);
        __syncthreads();
        const int item = s_item;
        __syncthreads();
        if (item >= FLASH_ITEMS) break;

        const int bh = item >> 5;
        const int q0 = (item & 31) * 128;
        const int b = bh >> 3, h = bh & 7;
        const size_t qrow0 = (size_t)bh * 4096 + q0;
        const size_t kvrow0 = (size_t)bh * 4096;

        if (tid == 0) {
            mbar_expect(qb, 32768u);
            bulk_g2s(smb + SVH, qh + qrow0 * 32, 16384u, qb);
            bulk_g2s(smb + SVL, ql + qrow0 * 32, 16384u, qb);
            mbar_expect(kb, 32768u);
            bulk_g2s(smb + SKH, kh + kvrow0 * 32, 16384u, kb);
            bulk_g2s(smb + SKL, kl + kvrow0 * 32, 16384u, kb);
        }
        mbar_wait(qb, qpar); qpar ^= 1;

        uint32_t qfh[4][4], qfl[4][4];
#pragma unroll
        for (int ds = 0; ds < 4; ++ds) {
            const uint32_t col = (uint32_t)(((s23 + 2 * ds) ^ r8) << 4);
            ldsm4(qfh[ds], smb + SVH + qrow + col);
            ldsm4(qfl[ds], smb + SVL + qrow + col);
        }
        __syncthreads();   // Q reads done: V region free for V(0)

        float o[8][4];
#pragma unroll
        for (int i = 0; i < 8; ++i)
#pragma unroll
            for (int j = 0; j < 4; ++j) o[i][j] = 0.f;
        float l0 = 0.f, l1 = 0.f;

        for (int i = 0; i < 32; ++i) {
            if (i) __syncthreads();            // O(i-1) reads of V done
            if (tid == 0) {
                mbar_expect(vb, 32768u);
                bulk_g2s(smb + SVH, vh + (kvrow0 + (size_t)i * 128) * 32,
                         16384u, vb);
                bulk_g2s(smb + SVL, vl + (kvrow0 + (size_t)i * 128) * 32,
                         16384u, vb);
            }
            mbar_wait(kb, kpar); kpar ^= 1;    // K(i) ready

#pragma unroll
            for (int c = 0; c < 4; ++c) {
                // ---- S chunk c ----
                const uint32_t kr = smb + krow + (uint32_t)(c * 32 * 128);
                float s[4][4];
#pragma unroll
                for (int nt = 0; nt < 4; ++nt)
#pragma unroll
                    for (int j = 0; j < 4; ++j) s[nt][j] = 0.f;
#pragma unroll
                for (int ds = 0; ds < 4; ++ds) {
                    const uint32_t col = (uint32_t)(((s01 + 2 * ds) ^ r8) << 4);
                    uint32_t b0[4], b1[4];
                    ldsm4(b0, kr + SKH + col);
                    ldsm4(b1, kr + SKH + 2048u + col);
                    mma16816(s[0], qfh[ds], b0[0], b0[1]);
                    mma16816(s[1], qfh[ds], b0[2], b0[3]);
                    mma16816(s[2], qfh[ds], b1[0], b1[1]);
                    mma16816(s[3], qfh[ds], b1[2], b1[3]);
                    mma16816(s[0], qfl[ds], b0[0], b0[1]);
                    mma16816(s[1], qfl[ds], b0[2], b0[3]);
                    mma16816(s[2], qfl[ds], b1[0], b1[1]);
                    mma16816(s[3], qfl[ds], b1[2], b1[3]);
                }
#pragma unroll
                for (int ds = 0; ds < 4; ++ds) {
                    const uint32_t col = (uint32_t)(((s01 + 2 * ds) ^ r8) << 4);
                    uint32_t b0[4], b1[4];
                    ldsm4(b0, kr + SKL + col);
                    ldsm4(b1, kr + SKL + 2048u + col);
                    mma16816(s[0], qfh[ds], b0[0], b0[1]);
                    mma16816(s[1], qfh[ds], b0[2], b0[3]);
                    mma16816(s[2], qfh[ds], b1[0], b1[1]);
                    mma16816(s[3], qfh[ds], b1[2], b1[3]);
                }

                if (c == 3) {
                    __syncthreads();
                    if (i < 31 && tid == 0) {
                        mbar_expect(kb, 32768u);
                        bulk_g2s(smb + SKH,
                                 kh + (kvrow0 + (size_t)(i + 1) * 128) * 32,
                                 16384u, kb);
                        bulk_g2s(smb + SKL,
                                 kl + (kvrow0 + (size_t)(i + 1) * 128) * 32,
                                 16384u, kb);
                    }
                }

                // ---- exp chunk c ----
                uint32_t phi[2][4], plo[2][4];
#pragma unroll
                for (int kk = 0; kk < 2; ++kk) {
#pragma unroll
                    for (int hb = 0; hb < 2; ++hb) {
                        const int nt = 2 * kk + hb;
                        float p0 = __expf(s[nt][0] - EXP_SHIFT);
                        float p1 = __expf(s[nt][1] - EXP_SHIFT);
                        float p2 = __expf(s[nt][2] - EXP_SHIFT);
                        float p3 = __expf(s[nt][3] - EXP_SHIFT);
                        l0 += p0 + p1;
                        l1 += p2 + p3;
                        uint32_t h01 = packbf(p0, p1), h23 = packbf(p2, p3);
                        phi[kk][hb * 2 + 0] = h01;
                        phi[kk][hb * 2 + 1] = h23;
                        plo[kk][hb * 2 + 0] = packbf(p0 - lof(h01), p1 - hif(h01));
                        plo[kk][hb * 2 + 1] = packbf(p2 - lof(h23), p3 - hif(h23));
                    }
                }
                if (c == 0) {
                    mbar_wait(vb, vpar); vpar ^= 1;   // V(i) ready
                }

                // ---- O chunk c ----
#pragma unroll
                for (int kk = 0; kk < 2; ++kk) {
                    const uint32_t vr = smb + vrow +
                                        (uint32_t)((c * 32 + kk * 16) * 128);
#pragma unroll
                    for (int mp = 0; mp < 2; ++mp) {
                        const int m0 = 2 * mp, m1 = 2 * mp + 1;
                        const uint32_t c0 = (uint32_t)(((s23 + 2 * m0) ^ r8) << 4);
                        const uint32_t c1 = (uint32_t)(((s23 + 2 * m1) ^ r8) << 4);
                        uint32_t vh0[4], vl0[4], vh1[4], vl1[4];
                        ldsm4t(vh0, vr + SVH + c0);
                        ldsm4t(vl0, vr + SVL + c0);
                        ldsm4t(vh1, vr + SVH + c1);
                        ldsm4t(vl1, vr + SVL + c1);
                        mma16816(o[2 * m0],     phi[kk], vh0[0], vh0[1]);
                        mma16816(o[2 * m0 + 1], phi[kk], vh0[2], vh0[3]);
                        mma16816(o[2 * m1],     phi[kk], vh1[0], vh1[1]);
                        mma16816(o[2 * m1 + 1], phi[kk], vh1[2], vh1[3]);
                        mma16816(o[2 * m0],     phi[kk], vl0[0], vl0[1]);
                        mma16816(o[2 * m0 + 1], phi[kk], vl0[2], vl0[3]);
                        mma16816(o[2 * m1],     phi[kk], vl1[0], vl1[1]);
                        mma16816(o[2 * m1 + 1], phi[kk], vl1[2], vl1[3]);
                        mma16816(o[2 * m0],     plo[kk], vh0[0], vh0[1]);
                        mma16816(o[2 * m0 + 1], plo[kk], vh0[2], vh0[3]);
                        mma16816(o[2 * m1],     plo[kk], vh1[0], vh1[1]);
                        mma16816(o[2 * m1 + 1], plo[kk], vh1[2], vh1[3]);
                    }
                }
            }
        }

        // Row sums over quad lanes
        l0 += __shfl_xor_sync(0xffffffffu, l0, 1);
        l0 += __shfl_xor_sync(0xffffffffu, l0, 2);
        l1 += __shfl_xor_sync(0xffffffffu, l1, 1);
        l1 += __shfl_xor_sync(0xffffffffu, l1, 2);
        const float inv0 = 1.f / l0, inv1 = 1.f / l1;

        // O epilogue: write k-block layout planes (input to gemm_out)
        const int row0 = b * 4096 + q0 + w * 16 + g;   // 0..8191
        const int row1 = row0 + 8;
        const int swz = (row0 >> 1) & 3;               // same for row0, row1
#pragma unroll
        for (int dt = 0; dt < 8; ++dt) {
            const int col = h * 32 + dt * 4 + tig;     // kp index 0..255
            const int kbi = col >> 4, kpi = col & 15;
            const int seg = (kpi >> 2) ^ swz;
            const size_t d0 = ((size_t)kbi * MROWS + row0) * 16 + seg * 4 + (kpi & 3);
            const size_t d1 = ((size_t)kbi * MROWS + row1) * 16 + seg * 4 + (kpi & 3);
            float a0 = o[dt][0] * inv0, a1 = o[dt][1] * inv0;
            float b0 = o[dt][2] * inv1, b1 = o[dt][3] * inv1;
            uint32_t h0 = packbf(a0, a1);
            uint32_t l0_ = packbf(a0 - lof(h0), a1 - hif(h0));
            uint32_t h1 = packbf(b0, b1);
            uint32_t l1_ = packbf(b0 - lof(h1), b1 - hif(h1));
            oh[d0] = h0; ol[d0] = l0_;
            oh[d1] = h1; ol[d1] = l1_;
        }
        __syncthreads();   // V(31) reads done before next item's Q staging
    }
}

// ---------------------------------------------------------------------------
extern "C" void kernel_launch(void* const* d_in, const int* in_sizes, int n_in,
                              void* d_out, int out_size)
{
    const float* inputs_q  = (const float*)d_in[0];
    const float* inputs_kv = (const float*)d_in[1];
    const float* Wq = (const float*)d_in[2];
    const float* Wk = (const float*)d_in[3];
    const float* Wv = (const float*)d_in[4];
    const float* Wo = (const float*)d_in[5];
    float* out = (float*)d_out;

    uint32_t *xqh, *xql, *xkvh, *xkvl;
    uint32_t *wqh, *wql, *wkh, *wkl, *wvh, *wvl, *woh, *wol;
    uint32_t *qh, *ql, *kh, *kl, *vh, *vl, *oh, *ol;
    cudaGetSymbolAddress((void**)&xqh, g_xq_h);   cudaGetSymbolAddress((void**)&xql, g_xq_l);
    cudaGetSymbolAddress((void**)&xkvh, g_xkv_h); cudaGetSymbolAddress((void**)&xkvl, g_xkv_l);
    cudaGetSymbolAddress((void**)&wqh, g_wq_h);   cudaGetSymbolAddress((void**)&wql, g_wq_l);
    cudaGetSymbolAddress((void**)&wkh, g_wk_h);   cudaGetSymbolAddress((void**)&wkl, g_wk_l);
    cudaGetSymbolAddress((void**)&wvh, g_wv_h);   cudaGetSymbolAddress((void**)&wvl, g_wv_l);
    cudaGetSymbolAddress((void**)&woh, g_wo_h);   cudaGetSymbolAddress((void**)&wol, g_wo_l);
    cudaGetSymbolAddress((void**)&qh, g_qh); cudaGetSymbolAddress((void**)&ql, g_ql);
    cudaGetSymbolAddress((void**)&kh, g_kh); cudaGetSymbolAddress((void**)&kl, g_kl);
    cudaGetSymbolAddress((void**)&vh, g_vh); cudaGetSymbolAddress((void**)&vl, g_vl);
    cudaGetSymbolAddress((void**)&oh, g_oh); cudaGetSymbolAddress((void**)&ol, g_ol);

    cudaFuncSetAttribute(gemm_qkv, cudaFuncAttributeMaxDynamicSharedMemorySize,
                         GEMM_SMEM);
    cudaFuncSetAttribute(gemm_out, cudaFuncAttributeMaxDynamicSharedMemorySize,
                         GEMM_SMEM);
    cudaFuncSetAttribute(flash_mma, cudaFuncAttributeMaxDynamicSharedMemorySize,
                         FLASH_SMEM);

    dim3 blk(256);

    // Prep (fused) + work counter reset
    reset_ctr<<<1, 1>>>();
    prep_act2<<<2 * MROWS, 256>>>(inputs_q, inputs_kv, xqh, xql, xkvh, xkvl);
    prep_w4<<<4 * 512, 256>>>(Wq, Wk, Wv, Wo,
                              wqh, wql, wkh, wkl, wvh, wvl, woh, wol);

    // Fused QKV projections -> flash-swizzled bf16 planes in [B,H,L,D]
    dim3 gQKV(FDIM / 128, MROWS / 128, 3);   // (4, 64, 3)
    gemm_qkv<<<gQKV, blk, GEMM_SMEM>>>(xqh, xql, xkvh, xkvl,
                                       wqh, wql, wkh, wkl, wvh, wvl,
                                       qh, ql, kh, kl, vh, vl);

    // Flash attention (persistent, work-stealing, bulk copies) -> O planes
    flash_mma<<<FLASH_GRID, blk, FLASH_SMEM>>>(qh, ql, kh, kl, vh, vl, oh, ol);

    // Output projection -> fp32 d_out
    dim3 gOut(FDIM / 128, MROWS / 128);      // (4, 64)
    gemm_out<<<gOut, blk, GEMM_SMEM>>>(oh, ol, woh, wol, out);
}

// round 17
// speedup vs baseline: 1.5406x; 1.5406x over previous
#include <cuda_runtime.h>
#include <cstdint>

// Problem constants
#define BATCH 2
#define QLEN  4096
#define FDIM  512
#define HEADS 8
#define DDIM  64
#define MROWS (BATCH * QLEN)          // 8192
#define BHROWS (BATCH * HEADS * QLEN) // 65536

// QKV-GEMM activation/weight planes: k-block layout [kb][row][16], swizzled
__device__ uint32_t g_xq_h[(size_t)MROWS * 256],  g_xq_l[(size_t)MROWS * 256];
__device__ uint32_t g_xkv_h[(size_t)MROWS * 256], g_xkv_l[(size_t)MROWS * 256];
__device__ uint32_t g_wq_h[512 * 256], g_wq_l[512 * 256];
__device__ uint32_t g_wk_h[512 * 256], g_wk_l[512 * 256];
__device__ uint32_t g_wv_h[512 * 256], g_wv_l[512 * 256];
// Wo planes: OLD row-major [n][256] (for CP16 gemm_out)
__device__ uint32_t g_wo_h[512 * 256], g_wo_l[512 * 256];
// Q/K/V planes: flash layout [row][32], 16B-seg XOR (row&7)
__device__ uint32_t g_qh[(size_t)BHROWS * 32], g_ql[(size_t)BHROWS * 32];
__device__ uint32_t g_kh[(size_t)BHROWS * 32], g_kl[(size_t)BHROWS * 32];
__device__ uint32_t g_vh[(size_t)BHROWS * 32], g_vl[(size_t)BHROWS * 32];
// O planes: row-major [row][256] (flash output, gemm_out input)
__device__ uint32_t g_oh[(size_t)MROWS * 256],  g_ol[(size_t)MROWS * 256];
__device__ int g_ctr;   // flash work-stealing counter

// ===========================================================================
// Helpers
// ===========================================================================
__device__ __forceinline__ uint32_t smem_u32(const void* p) {
    uint32_t a;
    asm("{ .reg .u64 t; cvta.to.shared.u64 t, %1; cvt.u32.u64 %0, t; }"
        : "=r"(a) : "l"(p));
    return a;
}
__device__ __forceinline__ uint32_t packbf(float a, float b) {  // low = a
    uint32_t r;
    asm("cvt.rn.bf16x2.f32 %0, %1, %2;" : "=r"(r) : "f"(b), "f"(a));
    return r;
}
__device__ __forceinline__ float lof(uint32_t h) { return __uint_as_float(h << 16); }
__device__ __forceinline__ float hif(uint32_t h) { return __uint_as_float(h & 0xffff0000u); }

__device__ __forceinline__ void ldsm4(uint32_t (&r)[4], uint32_t addr) {
    asm volatile("ldmatrix.sync.aligned.m8n8.x4.shared.b16 {%0,%1,%2,%3}, [%4];"
                 : "=r"(r[0]), "=r"(r[1]), "=r"(r[2]), "=r"(r[3]) : "r"(addr));
}
__device__ __forceinline__ void ldsm4t(uint32_t (&r)[4], uint32_t addr) {
    asm volatile("ldmatrix.sync.aligned.m8n8.x4.trans.shared.b16 {%0,%1,%2,%3}, [%4];"
                 : "=r"(r[0]), "=r"(r[1]), "=r"(r[2]), "=r"(r[3]) : "r"(addr));
}
__device__ __forceinline__ void mma16816(float (&d)[4], const uint32_t (&a)[4],
                                         uint32_t b0, uint32_t b1) {
    asm volatile(
        "mma.sync.aligned.m16n8k16.row.col.f32.bf16.bf16.f32 "
        "{%0,%1,%2,%3}, {%4,%5,%6,%7}, {%8,%9}, {%0,%1,%2,%3};"
        : "+f"(d[0]), "+f"(d[1]), "+f"(d[2]), "+f"(d[3])
        : "r"(a[0]), "r"(a[1]), "r"(a[2]), "r"(a[3]), "r"(b0), "r"(b1));
}
#define CP16(d, s) \
    asm volatile("cp.async.cg.shared.global [%0], [%1], 16;" :: "r"(d), "l"(s))
#define CP_COMMIT() asm volatile("cp.async.commit_group;" ::: "memory")
#define CP_WAIT(n)  asm volatile("cp.async.wait_group %0;" :: "n"(n) : "memory")

// mbarrier + bulk copy (sm_90 base)
__device__ __forceinline__ void mbar_init(uint32_t a, uint32_t n) {
    asm volatile("mbarrier.init.shared.b64 [%0], %1;" :: "r"(a), "r"(n) : "memory");
}
__device__ __forceinline__ void mbar_expect(uint32_t a, uint32_t bytes) {
    asm volatile("mbarrier.arrive.expect_tx.shared.b64 _, [%0], %1;"
                 :: "r"(a), "r"(bytes) : "memory");
}
__device__ __forceinline__ void mbar_wait(uint32_t a, uint32_t parity) {
    asm volatile(
        "{\n\t.reg .pred P;\n\t"
        "WL%=:\n\t"
        "mbarrier.try_wait.parity.acquire.cta.shared::cta.b64 P, [%0], %1, 0x989680;\n\t"
        "@P bra.uni WD%=;\n\t"
        "bra.uni WL%=;\n\t"
        "WD%=:\n\t}"
        :: "r"(a), "r"(parity) : "memory");
}
__device__ __forceinline__ void bulk_g2s(uint32_t dst, const void* src,
                                         uint32_t bytes, uint32_t mbar) {
    asm volatile(
        "cp.async.bulk.shared::cta.global.mbarrier::complete_tx::bytes "
        "[%0], [%1], %2, [%3];"
        :: "r"(dst), "l"(src), "r"(bytes), "r"(mbar) : "memory");
}

// ===========================================================================
// Prep
// ===========================================================================
__global__ void reset_ctr() { g_ctr = 0; }

// activations -> k-block layout [kb][row][16], seg-swizzled
__global__ void prep_act2(const float* __restrict__ s0, const float* __restrict__ s1,
                          uint32_t* __restrict__ h0, uint32_t* __restrict__ l0p,
                          uint32_t* __restrict__ h1, uint32_t* __restrict__ l1p) {
    int blk = blockIdx.x;
    int row = blk & (MROWS - 1);
    const float* src = (blk < MROWS) ? s0 : s1;
    uint32_t* dh = (blk < MROWS) ? h0 : h1;
    uint32_t* dl = (blk < MROWS) ? l0p : l1p;
    int kp = threadIdx.x;                 // 0..255
    float2 v = ((const float2*)src)[(size_t)row * 256 + kp];
    uint32_t h = packbf(v.x, v.y);
    uint32_t l = packbf(v.x - lof(h), v.y - hif(h));
    int kb = kp >> 4, kpi = kp & 15;
    int seg = (kpi >> 2) ^ ((row >> 1) & 3);
    size_t dst = ((size_t)kb * MROWS + row) * 16 + seg * 4 + (kpi & 3);
    dh[dst] = h;
    dl[dst] = l;
}
// Wq/Wk/Wv -> k-block; Wo -> OLD row-major [n][256]
__global__ void prep_w4(const float* __restrict__ W0, const float* __restrict__ W1,
                        const float* __restrict__ W2, const float* __restrict__ W3,
                        uint32_t* __restrict__ H0, uint32_t* __restrict__ L0,
                        uint32_t* __restrict__ H1, uint32_t* __restrict__ L1,
                        uint32_t* __restrict__ H2, uint32_t* __restrict__ L2,
                        uint32_t* __restrict__ H3, uint32_t* __restrict__ L3) {
    int blk = blockIdx.x;
    int sel = blk >> 9;
    const float* W = sel == 0 ? W0 : sel == 1 ? W1 : sel == 2 ? W2 : W3;
    uint32_t* dh   = sel == 0 ? H0 : sel == 1 ? H1 : sel == 2 ? H2 : H3;
    uint32_t* dl   = sel == 0 ? L0 : sel == 1 ? L1 : sel == 2 ? L2 : L3;
    int t = (blk & 511) * 256 + threadIdx.x;
    int n = t & 511, kp = t >> 9;
    float a = W[(size_t)(2 * kp) * 512 + n];
    float b = W[(size_t)(2 * kp + 1) * 512 + n];
    uint32_t h = packbf(a, b);
    uint32_t l = packbf(a - lof(h), b - hif(h));
    if (sel == 3) {   // Wo: row-major
        dh[n * 256 + kp] = h;
        dl[n * 256 + kp] = l;
    } else {          // k-block swizzled
        int kb = kp >> 4, kpi = kp & 15;
        int seg = (kpi >> 2) ^ ((n >> 1) & 3);
        size_t dst = ((size_t)kb * 512 + n) * 16 + seg * 4 + (kpi & 3);
        dh[dst] = h;
        dl[dst] = l;
    }
}

// ===========================================================================
// QKV GEMM: bulk-copy 2-deep pipeline (R16 version).
// Stage (32768B): AH 0 | AL 8192 | WH 16384 | WL 24576 ; packed 64B rows.
// ===========================================================================
#define GSTG 32768
#define GEMMB_SMEM (2 * GSTG)

__device__ __forceinline__ void gemm_bulk(
    uint32_t buf, int kb,
    const uint32_t* __restrict__ Ah, const uint32_t* __restrict__ Al,
    const uint32_t* __restrict__ Wh, const uint32_t* __restrict__ Wl,
    int rowBase, int colBase, uint32_t mb)
{
    mbar_expect(mb, 32768u);
    bulk_g2s(buf,          Ah + ((size_t)kb * MROWS + rowBase) * 16, 8192u, mb);
    bulk_g2s(buf + 8192u,  Al + ((size_t)kb * MROWS + rowBase) * 16, 8192u, mb);
    bulk_g2s(buf + 16384u, Wh + ((size_t)kb * 512 + colBase) * 16,   8192u, mb);
    bulk_g2s(buf + 24576u, Wl + ((size_t)kb * 512 + colBase) * 16,   8192u, mb);
}

__global__ __launch_bounds__(256, 2) void gemm_qkv(
    const uint32_t* __restrict__ xqh, const uint32_t* __restrict__ xql,
    const uint32_t* __restrict__ xkvh, const uint32_t* __restrict__ xkvl,
    const uint32_t* __restrict__ wqh, const uint32_t* __restrict__ wql,
    const uint32_t* __restrict__ wkh, const uint32_t* __restrict__ wkl,
    const uint32_t* __restrict__ wvh, const uint32_t* __restrict__ wvl,
    uint32_t* __restrict__ qh, uint32_t* __restrict__ ql,
    uint32_t* __restrict__ kh, uint32_t* __restrict__ kl,
    uint32_t* __restrict__ vh, uint32_t* __restrict__ vl)
{
    extern __shared__ char sm[];
    __shared__ __align__(8) unsigned long long gbar[2];
    const int tid = threadIdx.x;
    const int w = tid >> 5, lane = tid & 31;
    const int g = lane >> 2, tig = lane & 3;
    const int r8 = lane & 7;
    const int s01 = (lane >> 3) & 1;
    const int s23 = lane >> 4;
    const int rowBase = blockIdx.y * 128;
    const int colBase = blockIdx.x * 128;
    const int z = blockIdx.z;
    const int wm = w >> 1, wn = w & 1;

    const uint32_t smb = smem_u32(sm);
    const uint32_t mb0 = smem_u32(&gbar[0]);
    const uint32_t mb1 = smem_u32(&gbar[1]);
    if (tid == 0) { mbar_init(mb0, 1); mbar_init(mb1, 1); }
    __syncthreads();

    const uint32_t* Ah = (z == 0) ? xqh : xkvh;
    const uint32_t* Al = (z == 0) ? xql : xkvl;
    const uint32_t* Wh = (z == 0) ? wqh : (z == 1) ? wkh : wvh;
    const uint32_t* Wl = (z == 0) ? wql : (z == 1) ? wkl : wvl;
    uint32_t* Ch = (z == 0) ? qh : (z == 1) ? kh : vh;
    uint32_t* Cl = (z == 0) ? ql : (z == 1) ? kl : vl;

    float o[16][4];
#pragma unroll
    for (int i = 0; i < 16; ++i)
#pragma unroll
        for (int j = 0; j < 4; ++j) o[i][j] = 0.f;

    if (tid == 0) {
        gemm_bulk(smb,        0, Ah, Al, Wh, Wl, rowBase, colBase, mb0);
        gemm_bulk(smb + GSTG, 1, Ah, Al, Wh, Wl, rowBase, colBase, mb1);
    }
    int ph0 = 0, ph1 = 0;
    const int arow0 = wm * 32 + s01 * 8 + r8;
    const int arow1 = arow0 + 16;
    const uint32_t asw0 = (uint32_t)((arow0 >> 1) & 3);
    const uint32_t asw1 = (uint32_t)((arow1 >> 1) & 3);

    for (int it = 0; it < 16; ++it) {
        const uint32_t mb = (it & 1) ? mb1 : mb0;
        if (it & 1) { mbar_wait(mb, ph1); ph1 ^= 1; }
        else        { mbar_wait(mb, ph0); ph0 ^= 1; }
        const uint32_t bb = smb + (uint32_t)(it & 1) * GSTG;

#pragma unroll
        for (int kc = 0; kc < 2; ++kc) {
            uint32_t ah4[2][4], al4[2][4];
            {
                uint32_t a0 = bb + (uint32_t)(arow0 * 64) +
                              ((((uint32_t)(kc * 2) | (uint32_t)s23) ^ asw0) << 4);
                uint32_t a1 = bb + (uint32_t)(arow1 * 64) +
                              ((((uint32_t)(kc * 2) | (uint32_t)s23) ^ asw1) << 4);
                ldsm4(ah4[0], a0);
                ldsm4(al4[0], a0 + 8192u);
                ldsm4(ah4[1], a1);
                ldsm4(al4[1], a1 + 8192u);
            }
#pragma unroll
            for (int ng = 0; ng < 4; ++ng) {
                const int wrow = wn * 64 + ng * 16 + s23 * 8 + r8;
                const uint32_t wsw = (uint32_t)((wrow >> 1) & 3);
                const uint32_t wa = bb + 16384u + (uint32_t)(wrow * 64) +
                    ((((uint32_t)(kc * 2) | (uint32_t)s01) ^ wsw) << 4);
                uint32_t wh[4], wl[4];
                ldsm4(wh, wa);
                ldsm4(wl, wa + 8192u);
                mma16816(o[0 * 8 + ng * 2 + 0], ah4[0], wh[0], wh[1]);
                mma16816(o[0 * 8 + ng * 2 + 1], ah4[0], wh[2], wh[3]);
                mma16816(o[1 * 8 + ng * 2 + 0], ah4[1], wh[0], wh[1]);
                mma16816(o[1 * 8 + ng * 2 + 1], ah4[1], wh[2], wh[3]);
                mma16816(o[0 * 8 + ng * 2 + 0], al4[0], wh[0], wh[1]);
                mma16816(o[0 * 8 + ng * 2 + 1], al4[0], wh[2], wh[3]);
                mma16816(o[1 * 8 + ng * 2 + 0], al4[1], wh[0], wh[1]);
                mma16816(o[1 * 8 + ng * 2 + 1], al4[1], wh[2], wh[3]);
                mma16816(o[0 * 8 + ng * 2 + 0], ah4[0], wl[0], wl[1]);
                mma16816(o[0 * 8 + ng * 2 + 1], ah4[0], wl[2], wl[3]);
                mma16816(o[1 * 8 + ng * 2 + 0], ah4[1], wl[0], wl[1]);
                mma16816(o[1 * 8 + ng * 2 + 1], ah4[1], wl[2], wl[3]);
            }
        }
        __syncthreads();        // all reads of buf(it) done
        if (it + 2 < 16 && tid == 0)
            gemm_bulk(bb, it + 2, Ah, Al, Wh, Wl, rowBase, colBase, mb);
    }

#pragma unroll
    for (int dt = 0; dt < 16; ++dt) {
        const int mt = dt >> 3, ng = (dt >> 1) & 3, s = dt & 1;
        const int qr = rowBase + wm * 32 + mt * 16 + g;
        const int ncol = colBase + wn * 64 + ng * 16 + s * 8 + tig * 2;
        const int bb_ = qr >> 12;
        const int l = qr & 4095;
        const int hh = ncol >> 6;
        const int dpair = (ncol & 63) >> 1;
        const int dsw = ((((dpair >> 2) ^ (l & 7)) << 2) | (dpair & 3));
        const size_t prow0 = ((size_t)bb_ * HEADS + hh) * 4096 + l;
        const size_t prow1 = prow0 + 8;
        uint32_t h0 = packbf(o[dt][0], o[dt][1]);
        uint32_t l0_ = packbf(o[dt][0] - lof(h0), o[dt][1] - hif(h0));
        uint32_t h1 = packbf(o[dt][2], o[dt][3]);
        uint32_t l1_ = packbf(o[dt][2] - lof(h1), o[dt][3] - hif(h1));
        Ch[prow0 * 32 + dsw] = h0; Cl[prow0 * 32 + dsw] = l0_;
        Ch[prow1 * 32 + dsw] = h1; Cl[prow1 * 32 + dsw] = l1_;
    }
}

// ===========================================================================
// Output projection: R15 CP16 version (row-major A = g_oh, row-major Wo).
// Stage (40960B): AH 0|AL 10240|WH 20480|WL 30720 ; 80B rows.
// ===========================================================================
#define GBUF 40960
#define GEMMO_SMEM (2 * GBUF)

__device__ __forceinline__ void gemm_copy(
    uint32_t bb, const uint32_t* __restrict__ Ah, const uint32_t* __restrict__ Al,
    const uint32_t* __restrict__ Wh, const uint32_t* __restrict__ Wl,
    int rowBase, int colBase, int kc0, int tid)
{
#pragma unroll
    for (int j = 0; j < 8; ++j) {
        int c = j * 256 + tid;
        if (c < 1024) {
            int r = c >> 3, ww = c & 7, p = ww >> 2, seg = ww & 3;
            const uint32_t* src = (p ? Al : Ah) +
                (size_t)(rowBase + r) * 256 + kc0 + seg * 4;
            CP16(bb + (p ? 10240u : 0u) + r * 80 + seg * 16, src);
        } else {
            int c2 = c - 1024;
            int n = c2 >> 3, ww = c2 & 7, p = ww >> 2, seg = ww & 3;
            const uint32_t* src = (p ? Wl : Wh) +
                (size_t)(colBase + n) * 256 + kc0 + seg * 4;
            CP16(bb + 20480u + (p ? 10240u : 0u) + n * 80 + seg * 16, src);
        }
    }
}

__global__ __launch_bounds__(256, 2) void gemm_out(
    const uint32_t* __restrict__ Ah, const uint32_t* __restrict__ Al,
    const uint32_t* __restrict__ Wh, const uint32_t* __restrict__ Wl,
    float* __restrict__ Cf)
{
    extern __shared__ char sm[];
    const int tid = threadIdx.x;
    const int w = tid >> 5, lane = tid & 31;
    const int g = lane >> 2, tig = lane & 3;
    const int r8 = lane & 7;
    const int s01 = (lane >> 3) & 1;
    const int s23 = lane >> 4;
    const int rowBase = blockIdx.y * 128;
    const int colBase = blockIdx.x * 128;
    const int wm = w >> 1, wn = w & 1;

    const uint32_t smb = smem_u32(sm);
    const uint32_t aoff = (uint32_t)((wm * 32 + s01 * 8 + r8) * 80 + s23 * 16);
    const uint32_t woff = (uint32_t)((wn * 64 + s23 * 8 + r8) * 80 + s01 * 16);

    float o[16][4];
#pragma unroll
    for (int i = 0; i < 16; ++i)
#pragma unroll
        for (int j = 0; j < 4; ++j) o[i][j] = 0.f;

    gemm_copy(smb, Ah, Al, Wh, Wl, rowBase, colBase, 0, tid);
    CP_COMMIT();

    for (int it = 0; it < 16; ++it) {
        CP_WAIT(0);
        __syncthreads();
        if (it < 15) {
            gemm_copy(smb + (uint32_t)((it + 1) & 1) * GBUF, Ah, Al, Wh, Wl,
                      rowBase, colBase, (it + 1) * 16, tid);
            CP_COMMIT();
        }
        const uint32_t bb = smb + (uint32_t)(it & 1) * GBUF;

#pragma unroll
        for (int kc = 0; kc < 2; ++kc) {
            uint32_t ah4[2][4], al4[2][4];
#pragma unroll
            for (int mt = 0; mt < 2; ++mt) {
                ldsm4(ah4[mt], bb + aoff + mt * 16 * 80 + kc * 32);
                ldsm4(al4[mt], bb + 10240u + aoff + mt * 16 * 80 + kc * 32);
            }
#pragma unroll
            for (int ng = 0; ng < 4; ++ng) {
                uint32_t wh[4], wl[4];
                ldsm4(wh, bb + 20480u + woff + kc * 32 + ng * 16 * 80);
                ldsm4(wl, bb + 30720u + woff + kc * 32 + ng * 16 * 80);
                mma16816(o[0 * 8 + ng * 2 + 0], ah4[0], wh[0], wh[1]);
                mma16816(o[0 * 8 + ng * 2 + 1], ah4[0], wh[2], wh[3]);
                mma16816(o[1 * 8 + ng * 2 + 0], ah4[1], wh[0], wh[1]);
                mma16816(o[1 * 8 + ng * 2 + 1], ah4[1], wh[2], wh[3]);
                mma16816(o[0 * 8 + ng * 2 + 0], al4[0], wh[0], wh[1]);
                mma16816(o[0 * 8 + ng * 2 + 1], al4[0], wh[2], wh[3]);
                mma16816(o[1 * 8 + ng * 2 + 0], al4[1], wh[0], wh[1]);
                mma16816(o[1 * 8 + ng * 2 + 1], al4[1], wh[2], wh[3]);
                mma16816(o[0 * 8 + ng * 2 + 0], ah4[0], wl[0], wl[1]);
                mma16816(o[0 * 8 + ng * 2 + 1], ah4[0], wl[2], wl[3]);
                mma16816(o[1 * 8 + ng * 2 + 0], ah4[1], wl[0], wl[1]);
                mma16816(o[1 * 8 + ng * 2 + 1], ah4[1], wl[2], wl[3]);
            }
        }
    }

#pragma unroll
    for (int dt = 0; dt < 16; ++dt) {
        const int mt = dt >> 3, ng = (dt >> 1) & 3, s = dt & 1;
        const int qr = rowBase + wm * 32 + mt * 16 + g;
        const int n = colBase + wn * 64 + ng * 16 + s * 8 + tig * 2;
        float2 v0; v0.x = o[dt][0]; v0.y = o[dt][1];
        float2 v1; v1.x = o[dt][2]; v1.y = o[dt][3];
        *(float2*)(Cf + (size_t)qr * FDIM + n) = v0;
        *(float2*)(Cf + (size_t)(qr + 8) * FDIM + n) = v1;
    }
}

// ===========================================================================
// Flash attention: EXACT R15 version (bulk copies, row-major O epilogue).
// SMEM: K hi @0, K lo @16384, V hi @32768, V lo @49152
// ===========================================================================
#define EXP_SHIFT 30.0f
#define SKH 0u
#define SKL 16384u
#define SVH 32768u
#define SVL 49152u
#define FLASH_SMEM 65536
#define FLASH_ITEMS 512
#define FLASH_GRID 296

__global__ __launch_bounds__(256, 2) void flash_mma(
    const uint32_t* __restrict__ qh, const uint32_t* __restrict__ ql,
    const uint32_t* __restrict__ kh, const uint32_t* __restrict__ kl,
    const uint32_t* __restrict__ vh, const uint32_t* __restrict__ vl,
    uint32_t* __restrict__ oh, uint32_t* __restrict__ ol)
{
    extern __shared__ char sm[];
    __shared__ __align__(8) unsigned long long smbar[3];  // q, k, v
    __shared__ int s_item;
    const int tid = threadIdx.x;
    const int w = tid >> 5, lane = tid & 31;
    const int g = lane >> 2, tig = lane & 3;
    const int r8 = lane & 7;
    const int s01 = (lane >> 3) & 1;
    const int s23 = lane >> 4;

    const uint32_t smb = smem_u32(sm);
    const uint32_t qb = smem_u32(&smbar[0]);
    const uint32_t kb = smem_u32(&smbar[1]);
    const uint32_t vb = smem_u32(&smbar[2]);
    if (tid == 0) { mbar_init(qb, 1); mbar_init(kb, 1); mbar_init(vb, 1); }
    __syncthreads();
    int qpar = 0, kpar = 0, vpar = 0;

    const uint32_t qrow = (uint32_t)((w * 16 + s01 * 8 + r8) * 128);
    const uint32_t krow = (uint32_t)((s23 * 8 + r8) * 128);
    const uint32_t vrow = (uint32_t)((s01 * 8 + r8) * 128);

    while (true) {
        if (tid == 0) s_item = atomicAdd(&g_ctr, 1);
        __syncthreads();
        const int item = s_item;
        __syncthreads();
        if (item >= FLASH_ITEMS) break;

        const int bh = item >> 5;
        const int q0 = (item & 31) * 128;
        const int b = bh >> 3, h = bh & 7;
        const size_t qrow0 = (size_t)bh * 4096 + q0;
        const size_t kvrow0 = (size_t)bh * 4096;

        if (tid == 0) {
            mbar_expect(qb, 32768u);
            bulk_g2s(smb + SVH, qh + qrow0 * 32, 16384u, qb);
            bulk_g2s(smb + SVL, ql + qrow0 * 32, 16384u, qb);
            mbar_expect(kb, 32768u);
            bulk_g2s(smb + SKH, kh + kvrow0 * 32, 16384u, kb);
            bulk_g2s(smb + SKL, kl + kvrow0 * 32, 16384u, kb);
        }
        mbar_wait(qb, qpar); qpar ^= 1;

        uint32_t qfh[4][4], qfl[4][4];
#pragma unroll
        for (int ds = 0; ds < 4; ++ds) {
            const uint32_t col = (uint32_t)(((s23 + 2 * ds) ^ r8) << 4);
            ldsm4(qfh[ds], smb + SVH + qrow + col);
            ldsm4(qfl[ds], smb + SVL + qrow + col);
        }
        __syncthreads();   // Q reads done: V region free for V(0)

        float o[8][4];
#pragma unroll
        for (int i = 0; i < 8; ++i)
#pragma unroll
            for (int j = 0; j < 4; ++j) o[i][j] = 0.f;
        float l0 = 0.f, l1 = 0.f;

        for (int i = 0; i < 32; ++i) {
            if (i) __syncthreads();            // O(i-1) reads of V done
            if (tid == 0) {
                mbar_expect(vb, 32768u);
                bulk_g2s(smb + SVH, vh + (kvrow0 + (size_t)i * 128) * 32,
                         16384u, vb);
                bulk_g2s(smb + SVL, vl + (kvrow0 + (size_t)i * 128) * 32,
                         16384u, vb);
            }
            mbar_wait(kb, kpar); kpar ^= 1;    // K(i) ready

#pragma unroll
            for (int c = 0; c < 4; ++c) {
                // ---- S chunk c ----
                const uint32_t kr = smb + krow + (uint32_t)(c * 32 * 128);
                float s[4][4];
#pragma unroll
                for (int nt = 0; nt < 4; ++nt)
#pragma unroll
                    for (int j = 0; j < 4; ++j) s[nt][j] = 0.f;
#pragma unroll
                for (int ds = 0; ds < 4; ++ds) {
                    const uint32_t col = (uint32_t)(((s01 + 2 * ds) ^ r8) << 4);
                    uint32_t b0[4], b1[4];
                    ldsm4(b0, kr + SKH + col);
                    ldsm4(b1, kr + SKH + 2048u + col);
                    mma16816(s[0], qfh[ds], b0[0], b0[1]);
                    mma16816(s[1], qfh[ds], b0[2], b0[3]);
                    mma16816(s[2], qfh[ds], b1[0], b1[1]);
                    mma16816(s[3], qfh[ds], b1[2], b1[3]);
                    mma16816(s[0], qfl[ds], b0[0], b0[1]);
                    mma16816(s[1], qfl[ds], b0[2], b0[3]);
                    mma16816(s[2], qfl[ds], b1[0], b1[1]);
                    mma16816(s[3], qfl[ds], b1[2], b1[3]);
                }
#pragma unroll
                for (int ds = 0; ds < 4; ++ds) {
                    const uint32_t col = (uint32_t)(((s01 + 2 * ds) ^ r8) << 4);
                    uint32_t b0[4], b1[4];
                    ldsm4(b0, kr + SKL + col);
                    ldsm4(b1, kr + SKL + 2048u + col);
                    mma16816(s[0], qfh[ds], b0[0], b0[1]);
                    mma16816(s[1], qfh[ds], b0[2], b0[3]);
                    mma16816(s[2], qfh[ds], b1[0], b1[1]);
                    mma16816(s[3], qfh[ds], b1[2], b1[3]);
                }

                if (c == 3) {
                    __syncthreads();
                    if (i < 31 && tid == 0) {
                        mbar_expect(kb, 32768u);
                        bulk_g2s(smb + SKH,
                                 kh + (kvrow0 + (size_t)(i + 1) * 128) * 32,
                                 16384u, kb);
                        bulk_g2s(smb + SKL,
                                 kl + (kvrow0 + (size_t)(i + 1) * 128) * 32,
                                 16384u, kb);
                    }
                }

                // ---- exp chunk c ----
                uint32_t phi[2][4], plo[2][4];
#pragma unroll
                for (int kk = 0; kk < 2; ++kk) {
#pragma unroll
                    for (int hb = 0; hb < 2; ++hb) {
                        const int nt = 2 * kk + hb;
                        float p0 = __expf(s[nt][0] - EXP_SHIFT);
                        float p1 = __expf(s[nt][1] - EXP_SHIFT);
                        float p2 = __expf(s[nt][2] - EXP_SHIFT);
                        float p3 = __expf(s[nt][3] - EXP_SHIFT);
                        l0 += p0 + p1;
                        l1 += p2 + p3;
                        uint32_t h01 = packbf(p0, p1), h23 = packbf(p2, p3);
                        phi[kk][hb * 2 + 0] = h01;
                        phi[kk][hb * 2 + 1] = h23;
                        plo[kk][hb * 2 + 0] = packbf(p0 - lof(h01), p1 - hif(h01));
                        plo[kk][hb * 2 + 1] = packbf(p2 - lof(h23), p3 - hif(h23));
                    }
                }
                if (c == 0) {
                    mbar_wait(vb, vpar); vpar ^= 1;   // V(i) ready
                }

                // ---- O chunk c ----
#pragma unroll
                for (int kk = 0; kk < 2; ++kk) {
                    const uint32_t vr = smb + vrow +
                                        (uint32_t)((c * 32 + kk * 16) * 128);
#pragma unroll
                    for (int mp = 0; mp < 2; ++mp) {
                        const int m0 = 2 * mp, m1 = 2 * mp + 1;
                        const uint32_t c0 = (uint32_t)(((s23 + 2 * m0) ^ r8) << 4);
                        const uint32_t c1 = (uint32_t)(((s23 + 2 * m1) ^ r8) << 4);
                        uint32_t vh0[4], vl0[4], vh1[4], vl1[4];
                        ldsm4t(vh0, vr + SVH + c0);
                        ldsm4t(vl0, vr + SVL + c0);
                        ldsm4t(vh1, vr + SVH + c1);
                        ldsm4t(vl1, vr + SVL + c1);
                        mma16816(o[2 * m0],     phi[kk], vh0[0], vh0[1]);
                        mma16816(o[2 * m0 + 1], phi[kk], vh0[2], vh0[3]);
                        mma16816(o[2 * m1],     phi[kk], vh1[0], vh1[1]);
                        mma16816(o[2 * m1 + 1], phi[kk], vh1[2], vh1[3]);
                        mma16816(o[2 * m0],     phi[kk], vl0[0], vl0[1]);
                        mma16816(o[2 * m0 + 1], phi[kk], vl0[2], vl0[3]);
                        mma16816(o[2 * m1],     phi[kk], vl1[0], vl1[1]);
                        mma16816(o[2 * m1 + 1], phi[kk], vl1[2], vl1[3]);
                        mma16816(o[2 * m0],     plo[kk], vh0[0], vh0[1]);
                        mma16816(o[2 * m0 + 1], plo[kk], vh0[2], vh0[3]);
                        mma16816(o[2 * m1],     plo[kk], vh1[0], vh1[1]);
                        mma16816(o[2 * m1 + 1], plo[kk], vh1[2], vh1[3]);
                    }
                }
            }
        }

        // Row sums over quad lanes
        l0 += __shfl_xor_sync(0xffffffffu, l0, 1);
        l0 += __shfl_xor_sync(0xffffffffu, l0, 2);
        l1 += __shfl_xor_sync(0xffffffffu, l1, 1);
        l1 += __shfl_xor_sync(0xffffffffu, l1, 2);
        const float inv0 = 1.f / l0, inv1 = 1.f / l1;

        // O epilogue: row-major planes (R15)
        const size_t prow0 = (size_t)b * 4096 + q0 + w * 16 + g;
        const size_t prow1 = prow0 + 8;
#pragma unroll
        for (int dt = 0; dt < 8; ++dt) {
            const int col = h * 32 + dt * 4 + tig;
            float a0 = o[dt][0] * inv0, a1 = o[dt][1] * inv0;
            float b0 = o[dt][2] * inv1, b1 = o[dt][3] * inv1;
            uint32_t h0 = packbf(a0, a1);
            uint32_t l0_ = packbf(a0 - lof(h0), a1 - hif(h0));
            uint32_t h1 = packbf(b0, b1);
            uint32_t l1_ = packbf(b0 - lof(h1), b1 - hif(h1));
            oh[prow0 * 256 + col] = h0; ol[prow0 * 256 + col] = l0_;
            oh[prow1 * 256 + col] = h1; ol[prow1 * 256 + col] = l1_;
        }
        __syncthreads();   // V(31) reads done before next item's Q staging
    }
}

// ---------------------------------------------------------------------------
extern "C" void kernel_launch(void* const* d_in, const int* in_sizes, int n_in,
                              void* d_out, int out_size)
{
    const float* inputs_q  = (const float*)d_in[0];
    const float* inputs_kv = (const float*)d_in[1];
    const float* Wq = (const float*)d_in[2];
    const float* Wk = (const float*)d_in[3];
    const float* Wv = (const float*)d_in[4];
    const float* Wo = (const float*)d_in[5];
    float* out = (float*)d_out;

    uint32_t *xqh, *xql, *xkvh, *xkvl;
    uint32_t *wqh, *wql, *wkh, *wkl, *wvh, *wvl, *woh, *wol;
    uint32_t *qh, *ql, *kh, *kl, *vh, *vl, *oh, *ol;
    cudaGetSymbolAddress((void**)&xqh, g_xq_h);   cudaGetSymbolAddress((void**)&xql, g_xq_l);
    cudaGetSymbolAddress((void**)&xkvh, g_xkv_h); cudaGetSymbolAddress((void**)&xkvl, g_xkv_l);
    cudaGetSymbolAddress((void**)&wqh, g_wq_h);   cudaGetSymbolAddress((void**)&wql, g_wq_l);
    cudaGetSymbolAddress((void**)&wkh, g_wk_h);   cudaGetSymbolAddress((void**)&wkl, g_wk_l);
    cudaGetSymbolAddress((void**)&wvh, g_wv_h);   cudaGetSymbolAddress((void**)&wvl, g_wv_l);
    cudaGetSymbolAddress((void**)&woh, g_wo_h);   cudaGetSymbolAddress((void**)&wol, g_wo_l);
    cudaGetSymbolAddress((void**)&qh, g_qh); cudaGetSymbolAddress((void**)&ql, g_ql);
    cudaGetSymbolAddress((void**)&kh, g_kh); cudaGetSymbolAddress((void**)&kl, g_kl);
    cudaGetSymbolAddress((void**)&vh, g_vh); cudaGetSymbolAddress((void**)&vl, g_vl);
    cudaGetSymbolAddress((void**)&oh, g_oh); cudaGetSymbolAddress((void**)&ol, g_ol);

    cudaFuncSetAttribute(gemm_qkv, cudaFuncAttributeMaxDynamicSharedMemorySize,
                         GEMMB_SMEM);
    cudaFuncSetAttribute(gemm_out, cudaFuncAttributeMaxDynamicSharedMemorySize,
                         GEMMO_SMEM);
    cudaFuncSetAttribute(flash_mma, cudaFuncAttributeMaxDynamicSharedMemorySize,
                         FLASH_SMEM);

    dim3 blk(256);

    // Prep (fused) + work counter reset
    reset_ctr<<<1, 1>>>();
    prep_act2<<<2 * MROWS, 256>>>(inputs_q, inputs_kv, xqh, xql, xkvh, xkvl);
    prep_w4<<<4 * 512, 256>>>(Wq, Wk, Wv, Wo,
                              wqh, wql, wkh, wkl, wvh, wvl, woh, wol);

    // Fused QKV projections (bulk) -> flash-swizzled bf16 planes
    dim3 gQKV(FDIM / 128, MROWS / 128, 3);   // (4, 64, 3)
    gemm_qkv<<<gQKV, blk, GEMMB_SMEM>>>(xqh, xql, xkvh, xkvl,
                                        wqh, wql, wkh, wkl, wvh, wvl,
                                        qh, ql, kh, kl, vh, vl);

    // Flash attention (persistent, work-stealing, bulk copies) -> O planes
    flash_mma<<<FLASH_GRID, blk, FLASH_SMEM>>>(qh, ql, kh, kl, vh, vl, oh, ol);

    // Output projection (CP16, row-major inputs) -> fp32 d_out
    dim3 gOut(FDIM / 128, MROWS / 128);      // (4, 64)
    gemm_out<<<gOut, blk, GEMMO_SMEM>>>(oh, ol, woh, wol, out);
}